// round 9
// baseline (speedup 1.0000x reference)
#include <cuda_runtime.h>
#include <math.h>

// ---------------- problem constants ----------------
#define T_STEPS 16384
#define HDIM    1028
#define G4      4112          // 4*HDIM
#define KPAD    1032          // HDIM padded to multiple of 8 for GEMM
#define NCTA    129           // persistent CTAs: 129*8 = 1032 >= 1028 units
#define UPER    8             // hidden units per CTA (32 gate rows, 1 per lane)
#define NW      20            // warps per CTA
#define NT      640           // threads per CTA
#define CPW     52            // h-columns per warp: 20*52 = 1040 >= 1028
#define HB      1040          // staged h length (padded)
#define RREP    4             // h broadcast replicas (spread L2 slices)
#define RSTRIDE 1056          // floats between replicas (4224 B)
#define FPAD    32            // flag padding: 1 flag per 128B line (kill hot slices)

// ---------------- device scratch (static: no allocation allowed) ----------------
__device__ __align__(16) float g_h1[(long long)T_STEPS * KPAD];   // layer-0 outputs, K-padded
__device__ __align__(16) float g_ihc[(long long)T_STEPS * G4];    // w_ih1 @ h1  (precomputed)
__device__ __align__(16) float g_h2[(long long)T_STEPS * HDIM];   // layer-1 outputs
__device__ __align__(16) float g_hrep[2][RREP * RSTRIDE];         // double-buffered replicated h
__device__ __align__(16) float g_wpad[(long long)G4 * KPAD];      // padded w_ih1
__device__ unsigned g_ready[NCTA * FPAD];                         // per-CTA flags, 128B apart

// ---------------- pad w_ih1 to KPAD stride ----------------
__global__ void pad_w_kernel(const float* __restrict__ w) {
    int n = blockIdx.x;
    for (int k = threadIdx.x; k < KPAD; k += blockDim.x)
        g_wpad[(long long)n * KPAD + k] = (k < HDIM) ? w[(long long)n * HDIM + k] : 0.f;
}

// accurate activations (fast-math __expf drifts to ~4e-3 over 16384 recurrent
// steps -- measured in R5; library expf/tanhf give 3e-7 and only run on 8 lanes)
__device__ __forceinline__ float sigm(float x) { return 1.f / (1.f + expf(-x)); }

// ---------------- persistent LSTM recurrence ----------------
// 129 CTAs, 1/SM. CTA s owns units [s*8, s*8+8) -> 32 gate rows, one per lane.
// Warp w owns h-columns [w*52, w*52+52); recurrent weights in registers.
// Sync protocol (per step):
//   warp0: reduce + activations + replica stores + st.release.gpu flag
//   warp2: RELAXED poll of all 129 padded flags (pipelined loads), then one
//          fence.acq_rel.gpu. No acquire-per-load (R7 bug: acquire loads
//          serialize -> 2500-cyc poll iterations).
//   warp1: prefetch next step's input contribution.
__global__ void __launch_bounds__(NT, 1) lstm_rec_kernel(
    const float* __restrict__ w_hh,   // [4112][1028]
    const float* __restrict__ w_ih0,  // [4112] (layer 0 only)
    const float* __restrict__ b0,     // b_ih [4112]
    const float* __restrict__ b1,     // b_hh [4112]
    const float* __restrict__ xin,    // layer0: x[T]; layer1: g_ihc [T][4112]
    float* __restrict__ hout,         // layer0: g_h1 (stride KPAD); layer1: g_h2 (stride HDIM)
    int hstride, int layer)
{
    __shared__ float hs[HB];               // staged h for current step
    __shared__ float partial_s[NW * 32];
    __shared__ float xc_s[2][32];          // double-buffered input contribution

    const int tid = threadIdx.x;
    const int w   = tid >> 5;
    const int l   = tid & 31;
    const int s   = blockIdx.x;

    const int uu = l & 7;
    const int g  = l >> 3;
    const int u  = s * UPER + uu;
    const bool rowvalid = (u < HDIM);
    const int grow = g * HDIM + u;
    const int c0 = w * CPW;

    // --- one-time: recurrent weights into registers ---
    float wreg[CPW];
    #pragma unroll
    for (int j = 0; j < CPW; ++j) {
        int c = c0 + j;
        wreg[j] = (rowvalid && c < HDIM) ? w_hh[(long long)grow * HDIM + c] : 0.f;
    }
    float wih = 0.f, bsum = 0.f;
    if (rowvalid) {
        bsum = b0[grow] + b1[grow];
        if (layer == 0) wih = w_ih0[grow];
    }

    // --- init smem: h0 = 0, xc for t=0 ---
    for (int i = tid; i < HB; i += NT) hs[i] = 0.f;
    if (w == 1) {
        float v = 0.f;
        if (rowvalid)
            v = (layer == 0) ? fmaf(__ldg(&xin[0]), wih, bsum)
                             : __ldg(&xin[grow]) + bsum;
        xc_s[0][l] = v;
    }
    __syncthreads();

    const int rep = s & (RREP - 1);
    float creg = 0.f;   // cell state (warp 0, lanes < 8)

    for (int t = 0; t < T_STEPS; ++t) {
        // --- all warps: partial dot over own column chunk (SMEM broadcast) ---
        float a0 = 0.f, a1 = 0.f;
        #pragma unroll
        for (int j4 = 0; j4 < CPW / 4; ++j4) {
            float4 hv = *reinterpret_cast<const float4*>(&hs[c0 + 4 * j4]);
            a0 = fmaf(wreg[4 * j4 + 0], hv.x, a0);
            a1 = fmaf(wreg[4 * j4 + 1], hv.y, a1);
            a0 = fmaf(wreg[4 * j4 + 2], hv.z, a0);
            a1 = fmaf(wreg[4 * j4 + 3], hv.w, a1);
        }
        partial_s[(w << 5) + l] = a0 + a1;
        __syncthreads();

        if (w == 0) {
            // --- reduce across warps ---
            float sv = xc_s[t & 1][l];
            float s0 = 0.f, s1 = 0.f, s2 = 0.f, s3 = 0.f;
            #pragma unroll
            for (int ww = 0; ww < NW; ww += 4) {
                s0 += partial_s[((ww + 0) << 5) + l];
                s1 += partial_s[((ww + 1) << 5) + l];
                s2 += partial_s[((ww + 2) << 5) + l];
                s3 += partial_s[((ww + 3) << 5) + l];
            }
            sv += (s0 + s1) + (s2 + s3);
            // gather the 4 gates of unit (l&7): lanes uu, uu+8, uu+16, uu+24
            float iv = __shfl_sync(0xffffffffu, sv, uu + 0);
            float fv = __shfl_sync(0xffffffffu, sv, uu + 8);
            float gv = __shfl_sync(0xffffffffu, sv, uu + 16);
            float ov = __shfl_sync(0xffffffffu, sv, uu + 24);
            if (l < 8) {
                int uo = s * UPER + l;
                if (uo < HDIM) {
                    iv = sigm(iv);
                    fv = sigm(fv);
                    gv = tanhf(gv);
                    ov = sigm(ov);
                    float c2 = fmaf(fv, creg, iv * gv);
                    creg = c2;
                    float hh = ov * tanhf(c2);
                    float* dst = &g_hrep[(t + 1) & 1][0];
                    #pragma unroll
                    for (int r = 0; r < RREP; ++r)
                        __stcg(&dst[r * RSTRIDE + uo], hh);
                    hout[(long long)t * hstride + uo] = hh;
                }
            }
            __syncwarp();
            if (l == 0) {
                // release store: orders the h replica stores before the flag
                // (no separate __threadfence needed -- that was a MEMBAR.GPU
                // on the critical path in R7)
                unsigned tv = (unsigned)(t + 1);
                asm volatile("st.global.release.gpu.u32 [%0], %1;"
                             :: "l"(&g_ready[s * FPAD]), "r"(tv) : "memory");
            }
        } else if (w == 1) {
            // --- prefetch input contribution for t+1 ---
            if (t + 1 < T_STEPS) {
                float v = 0.f;
                if (rowvalid)
                    v = (layer == 0) ? fmaf(__ldg(&xin[t + 1]), wih, bsum)
                                     : __ldg(&xin[(long long)(t + 1) * G4 + grow]) + bsum;
                xc_s[(t + 1) & 1][l] = v;
            }
        } else if (w == 2) {
            // --- relaxed poll of all CTA flags (independent, pipelined) ---
            unsigned tgt = (unsigned)(t + 1);
            bool done = false;
            while (!done) {
                unsigned ok = 1u;
                #pragma unroll
                for (int k = 0; k < 5; ++k) {
                    int idx = l + 32 * k;
                    if (idx < NCTA) {
                        unsigned f;
                        asm volatile("ld.relaxed.gpu.global.u32 %0, [%1];"
                                     : "=r"(f) : "l"(&g_ready[idx * FPAD]) : "memory");
                        ok &= (f >= tgt) ? 1u : 0u;
                    }
                }
                done = (__all_sync(0xffffffffu, (int)ok) != 0);
            }
            // one acquire fence instead of per-load acquire
            asm volatile("fence.acq_rel.gpu;" ::: "memory");
        }
        __syncthreads();

        // --- stage h_{t+1} from buffer (t+1)&1: coalesced L2 read -> SMEM ---
        // (each warp stages exactly the chunk it will read; __syncwarp suffices)
        if (l < CPW / 4) {
            float4 hv = __ldcg(reinterpret_cast<const float4*>(
                               &g_hrep[(t + 1) & 1][rep * RSTRIDE + c0 + 4 * l]));
            *reinterpret_cast<float4*>(&hs[c0 + 4 * l]) = hv;
        }
        __syncwarp();
    }
}

// ---------------- fp32 SGEMM: g_ihc[T][4112] = g_h1[T][KPAD] * g_wpad[4112][KPAD]^T ----------------
__global__ void __launch_bounds__(256, 2) sgemm_kernel(float* __restrict__ C)
{
    __shared__ float As[8][128];
    __shared__ float Bs[8][128];

    const int tid = threadIdx.x;
    const int m0 = blockIdx.y * 128;
    const int n0 = blockIdx.x * 128;

    const int lr = tid >> 1;
    const int lc = (tid & 1) * 4;
    const float* Ap = g_h1 + (long long)(m0 + lr) * KPAD + lc;
    const int brow = n0 + lr;
    const float* Bp = g_wpad + (long long)brow * KPAD + lc;
    const bool bvalid = (brow < G4);

    const int tx = tid & 15;
    const int ty = tid >> 4;

    float acc[8][8];
    #pragma unroll
    for (int i = 0; i < 8; ++i)
        #pragma unroll
        for (int j = 0; j < 8; ++j) acc[i][j] = 0.f;

    for (int k0 = 0; k0 < KPAD; k0 += 8) {
        float4 av = *reinterpret_cast<const float4*>(Ap + k0);
        float4 bv = bvalid ? *reinterpret_cast<const float4*>(Bp + k0)
                           : make_float4(0.f, 0.f, 0.f, 0.f);
        __syncthreads();
        As[lc + 0][lr] = av.x; As[lc + 1][lr] = av.y;
        As[lc + 2][lr] = av.z; As[lc + 3][lr] = av.w;
        Bs[lc + 0][lr] = bv.x; Bs[lc + 1][lr] = bv.y;
        Bs[lc + 2][lr] = bv.z; Bs[lc + 3][lr] = bv.w;
        __syncthreads();
        #pragma unroll
        for (int kk = 0; kk < 8; ++kk) {
            float ra[8], rb[8];
            #pragma unroll
            for (int i = 0; i < 8; ++i) ra[i] = As[kk][ty * 8 + i];
            #pragma unroll
            for (int j = 0; j < 8; ++j) rb[j] = Bs[kk][tx * 8 + j];
            #pragma unroll
            for (int i = 0; i < 8; ++i)
                #pragma unroll
                for (int j = 0; j < 8; ++j)
                    acc[i][j] = fmaf(ra[i], rb[j], acc[i][j]);
        }
    }

    #pragma unroll
    for (int i = 0; i < 8; ++i) {
        int m = m0 + ty * 8 + i;
        #pragma unroll
        for (int j = 0; j < 8; ++j) {
            int n = n0 + tx * 8 + j;
            if (n < G4) C[(long long)m * G4 + n] = acc[i][j];
        }
    }
}

// ---------------- final linear: out[t] = h2[t] . lin_w + lin_b ----------------
__global__ void outdot_kernel(const float* __restrict__ lw,
                              const float* __restrict__ lb,
                              float* __restrict__ out)
{
    const int w = threadIdx.x >> 5;
    const int l = threadIdx.x & 31;
    const int t = blockIdx.x * 4 + w;
    if (t >= T_STEPS) return;
    const float* h = g_h2 + (long long)t * HDIM;
    float acc = 0.f;
    for (int u = l; u < HDIM; u += 32) acc = fmaf(h[u], lw[u], acc);
    #pragma unroll
    for (int o = 16; o; o >>= 1) acc += __shfl_down_sync(0xffffffffu, acc, o);
    if (l == 0) out[t] = acc + lb[0];
}

// ---------------- launch ----------------
extern "C" void kernel_launch(void* const* d_in, const int* in_sizes, int n_in,
                              void* d_out, int out_size)
{
    const float* x     = (const float*)d_in[0];
    const float* w_ih0 = (const float*)d_in[1];
    const float* w_hh0 = (const float*)d_in[2];
    const float* b_ih0 = (const float*)d_in[3];
    const float* b_hh0 = (const float*)d_in[4];
    const float* w_ih1 = (const float*)d_in[5];
    const float* w_hh1 = (const float*)d_in[6];
    const float* b_ih1 = (const float*)d_in[7];
    const float* b_hh1 = (const float*)d_in[8];
    const float* lin_w = (const float*)d_in[9];
    const float* lin_b = (const float*)d_in[10];
    float* out = (float*)d_out;

    void *p_h1, *p_ihc, *p_hrep, *p_ready, *p_h2;
    cudaGetSymbolAddress(&p_h1,    g_h1);
    cudaGetSymbolAddress(&p_ihc,   g_ihc);
    cudaGetSymbolAddress(&p_hrep,  g_hrep);
    cudaGetSymbolAddress(&p_ready, g_ready);
    cudaGetSymbolAddress(&p_h2,    g_h2);

    // zero: h1 (for K-padding), both h replica buffers, flags
    cudaMemsetAsync(p_h1,    0, sizeof(float) * (size_t)T_STEPS * KPAD);
    cudaMemsetAsync(p_hrep,  0, sizeof(float) * 2 * RREP * RSTRIDE);
    cudaMemsetAsync(p_ready, 0, sizeof(unsigned) * NCTA * FPAD);

    // pad w_ih1 for the GEMM
    pad_w_kernel<<<G4, 256>>>(w_ih1);

    // layer-0 recurrence
    lstm_rec_kernel<<<NCTA, NT>>>(w_hh0, w_ih0, b_ih0, b_hh0, x,
                                  (float*)p_h1, KPAD, 0);

    // ihc = h1 @ w_ih1^T (biases added inside recurrence kernel)
    dim3 gB(33, 128);
    sgemm_kernel<<<gB, 256>>>((float*)p_ihc);

    // reset flags + h replica buffers for layer 1
    cudaMemsetAsync(p_hrep,  0, sizeof(float) * 2 * RREP * RSTRIDE);
    cudaMemsetAsync(p_ready, 0, sizeof(unsigned) * NCTA * FPAD);

    // layer-1 recurrence
    lstm_rec_kernel<<<NCTA, NT>>>(w_hh1, nullptr, b_ih1, b_hh1,
                                  (const float*)p_ihc, (float*)p_h2, HDIM, 1);

    // final projection
    outdot_kernel<<<(T_STEPS + 3) / 4, 128>>>(lin_w, lin_b, out);
}

// round 10
// speedup vs baseline: 2.1932x; 2.1932x over previous
#include <cuda_runtime.h>
#include <math.h>

// ---------------- problem constants ----------------
#define T_STEPS 16384
#define HD      1028
#define NT      512           // 16 warps per CTA
#define NWP     16

// Layer 0: 49 CTAs x 21 units (49*21 = 1029 >= 1028). R0 = 84 gate rows.
#define N0   49
#define U0   21
#define GR0  2                // reg row-groups (rows 0..63)
#define RB0  20               // smem-only rows (rows 64..83)
#define CPW0 68               // cols per warp (16*68 = 1088 >= 1028), mult of 4
#define CR0  44               // reg cols per row-chunk
#define SC0  24               // smem cols for reg rows (CPW0-CR0)
#define DP0  1088             // staged vector length (NWP*CPW0)
#define RP0  96               // padded row count

// Layer 1: 94 CTAs x 11 units (94*11 = 1034 >= 1028). R1 = 44 gate rows.
// Input = concat [hb(1028) ; ha(1028)] -> D = 2056, padded 2112.
#define N1   94
#define U1   11
#define GR1  1                // reg rows 0..31
#define RB1  12               // smem rows 32..43
#define CPW1 132              // 16*132 = 2112 >= 2056, mult of 4
#define CR1  80
#define SC1  52
#define DP1  2112
#define RP1  48

#define NCTA_TOT (N0 + N1)    // 143 <= 148 SMs, all co-resident
#define RSTR 1088             // replica pitch (covers chunk padding reads)

// smem floats: DP + NWP*GRPS*32*SC + NWP*RB*CPW + NWP*RPAD + 3*RPAD
// L0: 1088+24576+21760+1536+288 = 49248  (196,992 B)
// L1: 2112+26624+25344+ 768+144 = 54992  (219,968 B)  <= 227KB limit
#define SMEM_BYTES 219968

// ---------------- device scratch ----------------
__device__ __align__(16) float g_h2[(long long)T_STEPS * HD];  // layer-1 outputs
__device__ __align__(16) float g_ha[2][4][RSTR];               // ha broadcast (parity x replica)
__device__ __align__(16) float g_hb[2][4][RSTR];               // hb broadcast
__device__ unsigned g_cnt;                                     // central round counter

extern __shared__ float dynsm[];

// ---------------- fused persistent 2-layer LSTM ----------------
// Round r (0..T): L0 computes ha[r] (active r<T); L1 computes hb[r-1] from
// [hb[r-2]; ha[r-1]] (active r>=1). Publish into parity (r+1)&1; one central
// REDG counter barrier per round. Double-buffered parity gives >=1 full
// barrier of slack between producer overwrite and laggard reads.
template<int LAYER, int U, int GRPS, int RB, int CPW, int CR, int SC,
         int DPAD, int RPAD>
__device__ __forceinline__ void run_layer(
    int cb,
    const float* __restrict__ wm0,   // L0: w_hh0 ; L1: w_hh1 (cols 0..HD)
    const float* __restrict__ wm1,   // L1: w_ih1 (cols HD..2HD) ; L0: unused
    const float* __restrict__ wih,   // L0: w_ih0 ; L1: unused
    const float* __restrict__ bA, const float* __restrict__ bB,
    const float* __restrict__ x)
{
    constexpr int R = GRPS * 32 + RB;   // = 4*U
    const int tid = threadIdx.x;
    const int w   = tid >> 5;
    const int l   = tid & 31;
    const int ub  = cb * U;
    const int c0  = w * CPW;

    float* hs     = dynsm;
    float* wA     = hs + DPAD;                    // reg-rows' smem leftover cols
    float* wB     = wA + NWP * GRPS * 32 * SC;    // smem-only rows, full chunks
    float* part   = wB + NWP * RB * CPW;          // partials [warp][RPAD]
    float* sums   = part + NWP * RPAD;
    float* bias_s = sums + RPAD;
    float* wih_s  = bias_s + RPAD;

    auto fetch = [&](int rr, int c) -> float {
        int gate = rr / U, uu = rr - gate * U;
        int gu = ub + uu;
        if (gu >= HD) return 0.f;
        long long row = (long long)gate * HD + gu;
        if (LAYER == 0) return (c < HD) ? wm0[row * HD + c] : 0.f;
        if (c < HD)      return wm0[row * HD + c];
        if (c < 2 * HD)  return wm1[row * HD + (c - HD)];
        return 0.f;
    };

    // ---- one-time weight load: regs + smem ----
    float wr[GRPS * CR];
    #pragma unroll
    for (int g = 0; g < GRPS; ++g) {
        int rr = g * 32 + l;
        #pragma unroll
        for (int j = 0; j < CR; ++j) wr[g * CR + j] = fetch(rr, c0 + j);
        for (int j = 0; j < SC; ++j)
            wA[((w * GRPS + g) * 32 + l) * SC + j] = fetch(rr, c0 + CR + j);
    }
    if (l < RB) {
        int rr = GRPS * 32 + l;
        for (int j = 0; j < CPW; ++j)
            wB[(w * RB + l) * CPW + j] = fetch(rr, c0 + j);
    }
    for (int rr = tid; rr < R; rr += NT) {
        int gate = rr / U, uu = rr - gate * U, gu = ub + uu;
        long long row = (long long)gate * HD + gu;
        bias_s[rr] = (gu < HD) ? bA[row] + bB[row] : 0.f;
        if (LAYER == 0) wih_s[rr] = (gu < HD) ? wih[row] : 0.f;
    }
    __syncthreads();

    const int rrep = blockIdx.x & 3;
    float creg = 0.f;   // cell state (warp 0, lanes < U)

    for (int r = 0; r <= T_STEPS; ++r) {
        const int p = r & 1;

        // ---- stage this warp's chunk of the input vector (L2 -> SMEM) ----
        for (int j4 = l; j4 < CPW / 4; j4 += 32) {
            int c = c0 + 4 * j4;
            const float4* src;
            if (LAYER == 0) src = (const float4*)&g_ha[p][rrep][c];
            else src = (c < HD) ? (const float4*)&g_hb[p][rrep][c]
                                : (const float4*)&g_ha[p][rrep][c - HD];
            float4 v = __ldcg(src);
            *(float4*)&hs[c] = v;
        }
        __syncwarp();

        // ---- partial dots: reg weights + smem weights ----
        float acc[GRPS];
        float accB = 0.f;
        #pragma unroll
        for (int g = 0; g < GRPS; ++g) acc[g] = 0.f;
        #pragma unroll
        for (int j4 = 0; j4 < CPW / 4; ++j4) {
            float4 hv = *(const float4*)&hs[c0 + 4 * j4];
            if (j4 < CR / 4) {
                #pragma unroll
                for (int g = 0; g < GRPS; ++g) {
                    acc[g] = fmaf(wr[g * CR + 4 * j4 + 0], hv.x, acc[g]);
                    acc[g] = fmaf(wr[g * CR + 4 * j4 + 1], hv.y, acc[g]);
                    acc[g] = fmaf(wr[g * CR + 4 * j4 + 2], hv.z, acc[g]);
                    acc[g] = fmaf(wr[g * CR + 4 * j4 + 3], hv.w, acc[g]);
                }
            } else {
                #pragma unroll
                for (int g = 0; g < GRPS; ++g) {
                    float4 wv = *(const float4*)
                        &wA[((w * GRPS + g) * 32 + l) * SC + (4 * j4 - CR)];
                    acc[g] = fmaf(wv.x, hv.x, acc[g]);
                    acc[g] = fmaf(wv.y, hv.y, acc[g]);
                    acc[g] = fmaf(wv.z, hv.z, acc[g]);
                    acc[g] = fmaf(wv.w, hv.w, acc[g]);
                }
            }
            if (l < RB) {
                float4 wv = *(const float4*)&wB[(w * RB + l) * CPW + 4 * j4];
                accB = fmaf(wv.x, hv.x, accB);
                accB = fmaf(wv.y, hv.y, accB);
                accB = fmaf(wv.z, hv.z, accB);
                accB = fmaf(wv.w, hv.w, accB);
            }
        }
        #pragma unroll
        for (int g = 0; g < GRPS; ++g) part[w * RPAD + g * 32 + l] = acc[g];
        if (l < RB) part[w * RPAD + GRPS * 32 + l] = accB;
        __syncthreads();

        if (w == 0) {
            // ---- reduce + bias (+x contribution for L0) ----
            float xv = 0.f;
            if (LAYER == 0) {
                if (l == 0 && r < T_STEPS) xv = __ldg(&x[r]);
                xv = __shfl_sync(0xffffffffu, xv, 0);
            }
            #pragma unroll
            for (int slot = 0; slot < GRPS + 1; ++slot) {
                int rr = slot * 32 + l;
                if (rr < R) {
                    float s = bias_s[rr];
                    if (LAYER == 0) s = fmaf(xv, wih_s[rr], s);
                    #pragma unroll
                    for (int ww = 0; ww < NWP; ++ww) s += part[ww * RPAD + rr];
                    sums[rr] = s;
                }
            }
            __syncwarp();
            // ---- gates, state update, publish ----
            const bool act = (LAYER == 0) ? (r < T_STEPS) : (r >= 1);
            if (l < U && act) {
                float iv = sums[l], fv = sums[U + l];
                float gv = sums[2 * U + l], ov = sums[3 * U + l];
                iv = 1.f / (1.f + expf(-iv));
                fv = 1.f / (1.f + expf(-fv));
                gv = tanhf(gv);
                ov = 1.f / (1.f + expf(-ov));
                float c2 = fmaf(fv, creg, iv * gv);
                creg = c2;
                float hh = ov * tanhf(c2);
                int gu = ub + l;
                if (gu < HD) {
                    if (LAYER == 0) {
                        #pragma unroll
                        for (int q = 0; q < 4; ++q) __stcg(&g_ha[p ^ 1][q][gu], hh);
                    } else {
                        #pragma unroll
                        for (int q = 0; q < 4; ++q) __stcg(&g_hb[p ^ 1][q][gu], hh);
                        g_h2[(long long)(r - 1) * HD + gu] = hh;
                    }
                }
            }
            __syncwarp();
            if (l == 0)
                asm volatile("red.release.gpu.global.add.u32 [%0], %1;"
                             :: "l"(&g_cnt), "r"(1u) : "memory");
        } else if (w == 1) {
            // ---- central-counter barrier: relaxed poll of ONE line ----
            if (l == 0) {
                unsigned tgt = (unsigned)(r + 1) * (unsigned)NCTA_TOT;
                unsigned v;
                do {
                    asm volatile("ld.relaxed.gpu.global.u32 %0, [%1];"
                                 : "=r"(v) : "l"(&g_cnt) : "memory");
                } while (v < tgt);
                asm volatile("fence.acq_rel.gpu;" ::: "memory");
            }
        }
        __syncthreads();
    }
}

__global__ void __launch_bounds__(NT, 1) fused_lstm_kernel(
    const float* __restrict__ x,
    const float* __restrict__ w_ih0, const float* __restrict__ w_hh0,
    const float* __restrict__ b_ih0, const float* __restrict__ b_hh0,
    const float* __restrict__ w_ih1, const float* __restrict__ w_hh1,
    const float* __restrict__ b_ih1, const float* __restrict__ b_hh1)
{
    if (blockIdx.x < N0)
        run_layer<0, U0, GR0, RB0, CPW0, CR0, SC0, DP0, RP0>(
            blockIdx.x, w_hh0, nullptr, w_ih0, b_ih0, b_hh0, x);
    else
        run_layer<1, U1, GR1, RB1, CPW1, CR1, SC1, DP1, RP1>(
            blockIdx.x - N0, w_hh1, w_ih1, nullptr, b_ih1, b_hh1, x);
}

// ---------------- final linear: out[t] = h2[t] . lin_w + lin_b ----------------
__global__ void outdot_kernel(const float* __restrict__ lw,
                              const float* __restrict__ lb,
                              float* __restrict__ out)
{
    const int w = threadIdx.x >> 5;
    const int l = threadIdx.x & 31;
    const int t = blockIdx.x * 4 + w;
    if (t >= T_STEPS) return;
    const float* h = g_h2 + (long long)t * HD;
    float acc = 0.f;
    for (int u = l; u < HD; u += 32) acc = fmaf(h[u], lw[u], acc);
    #pragma unroll
    for (int o = 16; o; o >>= 1) acc += __shfl_down_sync(0xffffffffu, acc, o);
    if (l == 0) out[t] = acc + lb[0];
}

// ---------------- launch ----------------
extern "C" void kernel_launch(void* const* d_in, const int* in_sizes, int n_in,
                              void* d_out, int out_size)
{
    const float* x     = (const float*)d_in[0];
    const float* w_ih0 = (const float*)d_in[1];
    const float* w_hh0 = (const float*)d_in[2];
    const float* b_ih0 = (const float*)d_in[3];
    const float* b_hh0 = (const float*)d_in[4];
    const float* w_ih1 = (const float*)d_in[5];
    const float* w_hh1 = (const float*)d_in[6];
    const float* b_ih1 = (const float*)d_in[7];
    const float* b_hh1 = (const float*)d_in[8];
    const float* lin_w = (const float*)d_in[9];
    const float* lin_b = (const float*)d_in[10];
    float* out = (float*)d_out;

    void *p_ha, *p_hb, *p_cnt;
    cudaGetSymbolAddress(&p_ha,  g_ha);
    cudaGetSymbolAddress(&p_hb,  g_hb);
    cudaGetSymbolAddress(&p_cnt, g_cnt);

    // zero broadcast buffers (h[-1] = 0, pad regions) and the round counter
    cudaMemsetAsync(p_ha,  0, sizeof(float) * 2 * 4 * RSTR);
    cudaMemsetAsync(p_hb,  0, sizeof(float) * 2 * 4 * RSTR);
    cudaMemsetAsync(p_cnt, 0, sizeof(unsigned));

    // opt-in to large dynamic smem (idempotent; capture-safe)
    cudaFuncSetAttribute(fused_lstm_kernel,
                         cudaFuncAttributeMaxDynamicSharedMemorySize, SMEM_BYTES);

    fused_lstm_kernel<<<NCTA_TOT, NT, SMEM_BYTES>>>(
        x, w_ih0, w_hh0, b_ih0, b_hh0, w_ih1, w_hh1, b_ih1, b_hh1);

    outdot_kernel<<<(T_STEPS + 3) / 4, 128>>>(lin_w, lin_b, out);
}